// round 4
// baseline (speedup 1.0000x reference)
#include <cuda_runtime.h>
#include <math.h>

// Problem constants
#define B_    2
#define C_    128
#define NN    784
#define INVT  0.08838834764831845f   // 1/sqrt(128)
#define INVC  0.0078125f             // 1/128

// ---------------- Distance kernel: attn[b,k,q] = mean_c |q/T - k| ----------------
#define DTILE 64
#define CSTEP 64
#define DPAD  4
#define DLD   (DTILE + DPAD)   // 68

__global__ __launch_bounds__(256) void dist_kernel(const float* __restrict__ q,
                                                   const float* __restrict__ k,
                                                   float* __restrict__ attn) {
    __shared__ float qS[CSTEP * DLD];
    __shared__ float kS[CSTEP * DLD];
    const int qt = blockIdx.x * DTILE;
    const int kt = blockIdx.y * DTILE;
    const int b  = blockIdx.z;
    const int tid = threadIdx.x;
    const int tx = tid & 15;    // q micro (4 values: tx*4 .. tx*4+3)
    const int ty = tid >> 4;    // k micro (4 values: ty*4 .. ty*4+3)

    const float* qb = q + (size_t)b * C_ * NN;
    const float* kb = k + (size_t)b * C_ * NN;

    float acc[4][4];
    #pragma unroll
    for (int j = 0; j < 4; j++)
        #pragma unroll
        for (int i = 0; i < 4; i++) acc[j][i] = 0.f;

    for (int cc = 0; cc < C_; cc += CSTEP) {
        // Stage CSTEP x DTILE tiles of q (scaled) and k, c-major-per-row layout.
        for (int i = tid; i < CSTEP * (DTILE / 4); i += 256) {
            int c    = i >> 4;     // 0..63
            int col4 = i & 15;     // 0..15
            int gq = qt + col4 * 4;
            int gk = kt + col4 * 4;
            float4 qv = make_float4(0.f, 0.f, 0.f, 0.f);
            float4 kv = make_float4(0.f, 0.f, 0.f, 0.f);
            if (gq < NN) qv = *(const float4*)&qb[(size_t)(cc + c) * NN + gq];
            if (gk < NN) kv = *(const float4*)&kb[(size_t)(cc + c) * NN + gk];
            float* qr = &qS[c * DLD + col4 * 4];
            qr[0] = qv.x * INVT; qr[1] = qv.y * INVT; qr[2] = qv.z * INVT; qr[3] = qv.w * INVT;
            float* kr = &kS[c * DLD + col4 * 4];
            kr[0] = kv.x; kr[1] = kv.y; kr[2] = kv.z; kr[3] = kv.w;
        }
        __syncthreads();

        #pragma unroll 4
        for (int c = 0; c < CSTEP; c++) {
            float4 qv = *(const float4*)&qS[c * DLD + tx * 4];
            float4 kv = *(const float4*)&kS[c * DLD + ty * 4];
            float qa[4] = {qv.x, qv.y, qv.z, qv.w};
            float ka[4] = {kv.x, kv.y, kv.z, kv.w};
            #pragma unroll
            for (int j = 0; j < 4; j++)
                #pragma unroll
                for (int i = 0; i < 4; i++)
                    acc[j][i] += fabsf(qa[i] - ka[j]);
        }
        __syncthreads();
    }

    float* ab = attn + (size_t)b * NN * NN;
    const int gq = qt + tx * 4;
    #pragma unroll
    for (int j = 0; j < 4; j++) {
        int gk = kt + ty * 4 + j;
        if (gk < NN && gq < NN) {
            float4 o = make_float4(acc[j][0] * INVC, acc[j][1] * INVC,
                                   acc[j][2] * INVC, acc[j][3] * INVC);
            *(float4*)&ab[(size_t)gk * NN + gq] = o;
        }
    }
}

// ---------------- Softmax over last dim (q), in place, one block per row -------
__global__ __launch_bounds__(256) void softmax_kernel(float* __restrict__ attn) {
    __shared__ float red[32];
    const int row = blockIdx.x;             // b*NN + k
    float* p = attn + (size_t)row * NN;
    const int tid = threadIdx.x;

    float v[4];
    float mx = -1e30f;
    #pragma unroll
    for (int i = 0; i < 4; i++) {
        int idx = tid + i * 256;
        v[i] = (idx < NN) ? p[idx] : -1e30f;
        mx = fmaxf(mx, v[i]);
    }
    #pragma unroll
    for (int o = 16; o > 0; o >>= 1) mx = fmaxf(mx, __shfl_xor_sync(0xffffffffu, mx, o));
    if ((tid & 31) == 0) red[tid >> 5] = mx;
    __syncthreads();
    if (tid < 32) {
        float m = (tid < 8) ? red[tid] : -1e30f;
        #pragma unroll
        for (int o = 4; o > 0; o >>= 1) m = fmaxf(m, __shfl_xor_sync(0xffffffffu, m, o));
        if (tid == 0) red[0] = m;
    }
    __syncthreads();
    mx = red[0];
    __syncthreads();

    float s = 0.f;
    #pragma unroll
    for (int i = 0; i < 4; i++) {
        v[i] = __expf(v[i] - mx);   // -1e30 path underflows to 0
        s += v[i];
    }
    #pragma unroll
    for (int o = 16; o > 0; o >>= 1) s += __shfl_xor_sync(0xffffffffu, s, o);
    if ((tid & 31) == 0) red[tid >> 5] = s;
    __syncthreads();
    if (tid < 32) {
        float m = (tid < 8) ? red[tid] : 0.f;
        #pragma unroll
        for (int o = 4; o > 0; o >>= 1) m += __shfl_xor_sync(0xffffffffu, m, o);
        if (tid == 0) red[0] = m;
    }
    __syncthreads();
    const float inv = 1.f / red[0];
    #pragma unroll
    for (int i = 0; i < 4; i++) {
        int idx = tid + i * 256;
        if (idx < NN) p[idx] = v[i] * inv;
    }
}

// ---------------- GEMM: out[b,c,k] = sum_q v[b,c,q] * attn[b,k,q] --------------
#define TM 64      // c tile
#define TN 32      // k tile
#define TQ 32      // q (inner) tile
#define LDV (TM + 4)   // 68
#define LDA (TN + 4)   // 36

__global__ __launch_bounds__(256) void gemm_kernel(const float* __restrict__ v,
                                                   const float* __restrict__ attn,
                                                   float* __restrict__ out) {
    __shared__ float vS[TQ * LDV];
    __shared__ float aS[TQ * LDA];
    const int k0 = blockIdx.x * TN;
    const int c0 = blockIdx.y * TM;
    const int b  = blockIdx.z;
    const int tid = threadIdx.x;
    const int tx = tid & 15;    // k micro (2 values)
    const int ty = tid >> 4;    // c micro (4 values)

    const float* vb = v    + (size_t)b * C_ * NN;
    const float* ab = attn + (size_t)b * NN * NN;

    float acc[4][2] = {{0.f,0.f},{0.f,0.f},{0.f,0.f},{0.f,0.f}};

    for (int q0 = 0; q0 < NN; q0 += TQ) {
        // vS[q][c]: TM rows x TQ cols from v, stored q-major
        for (int i = tid; i < TM * (TQ / 4); i += 256) {
            int c  = i >> 3;     // 0..63
            int q4 = i & 7;      // 0..7
            int gq = q0 + q4 * 4;
            float4 t = make_float4(0.f, 0.f, 0.f, 0.f);
            if (gq < NN) t = *(const float4*)&vb[(size_t)(c0 + c) * NN + gq];
            vS[(q4 * 4 + 0) * LDV + c] = t.x;
            vS[(q4 * 4 + 1) * LDV + c] = t.y;
            vS[(q4 * 4 + 2) * LDV + c] = t.z;
            vS[(q4 * 4 + 3) * LDV + c] = t.w;
        }
        // aS[q][k]: TN rows x TQ cols from attn
        {
            int kk = tid >> 3;   // 0..31
            int q4 = tid & 7;    // 0..7
            int gq = q0 + q4 * 4;
            int gk = k0 + kk;
            float4 t = make_float4(0.f, 0.f, 0.f, 0.f);
            if (gq < NN && gk < NN) t = *(const float4*)&ab[(size_t)gk * NN + gq];
            aS[(q4 * 4 + 0) * LDA + kk] = t.x;
            aS[(q4 * 4 + 1) * LDA + kk] = t.y;
            aS[(q4 * 4 + 2) * LDA + kk] = t.z;
            aS[(q4 * 4 + 3) * LDA + kk] = t.w;
        }
        __syncthreads();

        #pragma unroll 8
        for (int qq = 0; qq < TQ; qq++) {
            float4 vv = *(const float4*)&vS[qq * LDV + ty * 4];
            float2 av = *(const float2*)&aS[qq * LDA + tx * 2];
            acc[0][0] += vv.x * av.x;  acc[0][1] += vv.x * av.y;
            acc[1][0] += vv.y * av.x;  acc[1][1] += vv.y * av.y;
            acc[2][0] += vv.z * av.x;  acc[2][1] += vv.z * av.y;
            acc[3][0] += vv.w * av.x;  acc[3][1] += vv.w * av.y;
        }
        __syncthreads();
    }

    float* ob = out + (size_t)b * C_ * NN;
    #pragma unroll
    for (int i = 0; i < 4; i++) {
        int c = c0 + ty * 4 + i;
        #pragma unroll
        for (int j = 0; j < 2; j++) {
            int gk = k0 + tx * 2 + j;
            if (gk < NN) ob[(size_t)c * NN + gk] = acc[i][j];
        }
    }
}

// ---------------- Launch ---------------------------------------------------------
extern "C" void kernel_launch(void* const* d_in, const int* in_sizes, int n_in,
                              void* d_out, int out_size) {
    const float* q = (const float*)d_in[0];
    const float* k = (const float*)d_in[1];
    const float* v = (const float*)d_in[2];
    float* out  = (float*)d_out;                      // [B, C, N]
    float* attn = out + (size_t)B_ * C_ * NN;         // [B, N, N]

    (void)in_sizes; (void)n_in; (void)out_size;

    // 1) L1 distance logits -> attn region
    dim3 dgrid((NN + DTILE - 1) / DTILE, (NN + DTILE - 1) / DTILE, B_);  // 13,13,2
    dist_kernel<<<dgrid, 256>>>(q, k, attn);

    // 2) softmax over q, in place
    softmax_kernel<<<B_ * NN, 256>>>(attn);

    // 3) out = v @ attn^T (per batch)
    dim3 ggrid((NN + TN - 1) / TN, C_ / TM, B_);      // 25,2,2
    gemm_kernel<<<ggrid, 256>>>(v, attn, out);
}

// round 5
// speedup vs baseline: 1.0851x; 1.0851x over previous
#include <cuda_runtime.h>
#include <math.h>

// Problem constants
#define B_    2
#define C_    128
#define NN    784
#define INVT  0.08838834764831845f   // 1/sqrt(128)
#define INVC  0.0078125f             // 1/128

typedef unsigned long long ull;
#define ABS2MASK 0x7FFFFFFF7FFFFFFFULL

// ---------------- Distance kernel: attn[b,k,q] = mean_c |q/T - k| ----------------
// Packed f32x2: kS holds -k DUPLICATED (pairs), qS holds q/T. diff = add.f32x2,
// abs = 64-bit AND mask (2x LOP3, alu pipe), acc = add.f32x2. fma-pipe work halves.
#define DTILE 64
#define CSTEP 32
#define QLD   68     // 64 + 4 pad (floats)
#define KLD   132    // 128 dup + 4 pad (floats)

__global__ __launch_bounds__(256) void dist_kernel(const float* __restrict__ q,
                                                   const float* __restrict__ k,
                                                   float* __restrict__ attn) {
    __shared__ float qS[CSTEP * QLD];
    __shared__ float kS[CSTEP * KLD];
    const int qt = blockIdx.x * DTILE;
    const int kt = blockIdx.y * DTILE;
    const int b  = blockIdx.z;
    const int tid = threadIdx.x;
    const int tx = tid & 15;    // q micro: 4 values at tx*4  (2 packed pairs)
    const int ty = tid >> 4;    // k micro: 4 values at ty*4

    const float* qb = q + (size_t)b * C_ * NN;
    const float* kb = k + (size_t)b * C_ * NN;

    ull acc[4][2];
    #pragma unroll
    for (int j = 0; j < 4; j++) { acc[j][0] = 0ULL; acc[j][1] = 0ULL; }

    for (int cc = 0; cc < C_; cc += CSTEP) {
        // Stage: 512 float4 loads each for q and k, spread over 256 threads.
        #pragma unroll
        for (int t = 0; t < 2; t++) {
            int i = tid + t * 256;          // 0..511
            int c    = i >> 4;              // 0..31
            int col4 = i & 15;              // 0..15
            int gq = qt + col4 * 4;
            int gk = kt + col4 * 4;
            float4 qv = make_float4(0.f, 0.f, 0.f, 0.f);
            float4 kv = make_float4(0.f, 0.f, 0.f, 0.f);
            if (gq < NN) qv = *(const float4*)&qb[(size_t)(cc + c) * NN + gq];
            if (gk < NN) kv = *(const float4*)&kb[(size_t)(cc + c) * NN + gk];
            float* qr = &qS[c * QLD + col4 * 4];
            qr[0] = qv.x * INVT; qr[1] = qv.y * INVT;
            qr[2] = qv.z * INVT; qr[3] = qv.w * INVT;
            float2* kr = (float2*)&kS[c * KLD + col4 * 8];
            kr[0] = make_float2(-kv.x, -kv.x);
            kr[1] = make_float2(-kv.y, -kv.y);
            kr[2] = make_float2(-kv.z, -kv.z);
            kr[3] = make_float2(-kv.w, -kv.w);
        }
        __syncthreads();

        #pragma unroll 4
        for (int c = 0; c < CSTEP; c++) {
            const ull qp0 = *(const ull*)&qS[c * QLD + tx * 4];
            const ull qp1 = *(const ull*)&qS[c * QLD + tx * 4 + 2];
            #pragma unroll
            for (int j = 0; j < 4; j++) {
                const ull kp = *(const ull*)&kS[c * KLD + (ty * 4 + j) * 2];
                ull d0, d1;
                asm("add.rn.f32x2 %0, %1, %2;" : "=l"(d0) : "l"(qp0), "l"(kp));
                asm("add.rn.f32x2 %0, %1, %2;" : "=l"(d1) : "l"(qp1), "l"(kp));
                d0 &= ABS2MASK;
                d1 &= ABS2MASK;
                asm("add.rn.f32x2 %0, %0, %1;" : "+l"(acc[j][0]) : "l"(d0));
                asm("add.rn.f32x2 %0, %0, %1;" : "+l"(acc[j][1]) : "l"(d1));
            }
        }
        __syncthreads();
    }

    float* ab = attn + (size_t)b * NN * NN;
    const int gq = qt + tx * 4;
    if (gq < NN) {
        #pragma unroll
        for (int j = 0; j < 4; j++) {
            int gk = kt + ty * 4 + j;
            if (gk < NN) {
                float4 o;
                o.x = __uint_as_float((unsigned)(acc[j][0] & 0xffffffffu)) * INVC;
                o.y = __uint_as_float((unsigned)(acc[j][0] >> 32))         * INVC;
                o.z = __uint_as_float((unsigned)(acc[j][1] & 0xffffffffu)) * INVC;
                o.w = __uint_as_float((unsigned)(acc[j][1] >> 32))         * INVC;
                *(float4*)&ab[(size_t)gk * NN + gq] = o;
            }
        }
    }
}

// ---------------- Softmax over last dim (q), in place, one block per row -------
__global__ __launch_bounds__(256) void softmax_kernel(float* __restrict__ attn) {
    __shared__ float red[8];
    const int row = blockIdx.x;             // b*NN + k
    float* p = attn + (size_t)row * NN;
    const int tid  = threadIdx.x;
    const bool act = (tid < NN / 4);        // 196 active lanes

    float4 v = make_float4(-1e30f, -1e30f, -1e30f, -1e30f);
    if (act) v = ((const float4*)p)[tid];

    float mx = fmaxf(fmaxf(v.x, v.y), fmaxf(v.z, v.w));
    #pragma unroll
    for (int o = 16; o > 0; o >>= 1) mx = fmaxf(mx, __shfl_xor_sync(0xffffffffu, mx, o));
    if ((tid & 31) == 0) red[tid >> 5] = mx;
    __syncthreads();
    if (tid < 32) {
        float m = (tid < 8) ? red[tid] : -1e30f;
        #pragma unroll
        for (int o = 4; o > 0; o >>= 1) m = fmaxf(m, __shfl_xor_sync(0xffffffffu, m, o));
        if (tid == 0) red[0] = m;
    }
    __syncthreads();
    mx = red[0];
    __syncthreads();

    v.x = __expf(v.x - mx); v.y = __expf(v.y - mx);
    v.z = __expf(v.z - mx); v.w = __expf(v.w - mx);
    float s = act ? (v.x + v.y) + (v.z + v.w) : 0.f;
    #pragma unroll
    for (int o = 16; o > 0; o >>= 1) s += __shfl_xor_sync(0xffffffffu, s, o);
    if ((tid & 31) == 0) red[tid >> 5] = s;
    __syncthreads();
    if (tid < 32) {
        float m = (tid < 8) ? red[tid] : 0.f;
        #pragma unroll
        for (int o = 4; o > 0; o >>= 1) m += __shfl_xor_sync(0xffffffffu, m, o);
        if (tid == 0) red[0] = m;
    }
    __syncthreads();
    const float inv = 1.f / red[0];
    if (act) {
        v.x *= inv; v.y *= inv; v.z *= inv; v.w *= inv;
        ((float4*)p)[tid] = v;
    }
}

// ---------------- GEMM: out[b,c,k] = sum_q v[b,c,q] * attn[b,k,q] --------------
// Packed fma.rn.f32x2, split-Q x3 with atomicAdd epilogue (out memset to 0 first).
#define GBN   32      // k tile
#define GBQ   16      // q staging depth
#define QSPL  264     // q per split (264,264,256)
#define VLD   264     // 128 c duplicated (256) + 8 pad
#define ALD   36      // 32 + 4 pad

__global__ __launch_bounds__(256) void gemm_kernel(const float* __restrict__ v,
                                                   const float* __restrict__ attn,
                                                   float* __restrict__ out) {
    __shared__ float vS[GBQ * VLD];   // duplicated v: [q][2*c]
    __shared__ float aS[GBQ * ALD];   // [q][k]
    const int k0 = blockIdx.x * GBN;
    const int qs = blockIdx.y * QSPL;
    const int qe = min(qs + QSPL, NN);
    const int b  = blockIdx.z;
    const int tid = threadIdx.x;
    const int tx = tid & 15;          // k pair: k0 + tx*2, +1
    const int ty = tid >> 4;          // c: ty*8 .. ty*8+7

    const float* vb = v    + (size_t)b * C_ * NN;
    const float* ab = attn + (size_t)b * NN * NN;

    ull acc[8];
    #pragma unroll
    for (int i = 0; i < 8; i++) acc[i] = 0ULL;

    for (int q0 = qs; q0 < qe; q0 += GBQ) {
        // Stage v (duplicated): 16 q x 128 c = 512 float4 loads
        #pragma unroll
        for (int t = 0; t < 2; t++) {
            int i  = tid + t * 256;       // 0..511
            int c  = i >> 2;              // 0..127
            int q4 = i & 3;               // 0..3
            int gq = q0 + q4 * 4;
            float4 tv = make_float4(0.f, 0.f, 0.f, 0.f);
            if (gq < qe) tv = *(const float4*)&vb[(size_t)c * NN + gq];
            *(float2*)&vS[(q4 * 4 + 0) * VLD + c * 2] = make_float2(tv.x, tv.x);
            *(float2*)&vS[(q4 * 4 + 1) * VLD + c * 2] = make_float2(tv.y, tv.y);
            *(float2*)&vS[(q4 * 4 + 2) * VLD + c * 2] = make_float2(tv.z, tv.z);
            *(float2*)&vS[(q4 * 4 + 3) * VLD + c * 2] = make_float2(tv.w, tv.w);
        }
        // Stage a: 16 q x 32 k = 128 float4 loads (threads 0..127)
        if (tid < 128) {
            int kk = tid >> 2;            // 0..31
            int q4 = tid & 3;             // 0..3
            int gq = q0 + q4 * 4;
            int gk = k0 + kk;
            float4 ta = make_float4(0.f, 0.f, 0.f, 0.f);
            if (gq < qe && gk < NN) ta = *(const float4*)&ab[(size_t)gk * NN + gq];
            aS[(q4 * 4 + 0) * ALD + kk] = ta.x;
            aS[(q4 * 4 + 1) * ALD + kk] = ta.y;
            aS[(q4 * 4 + 2) * ALD + kk] = ta.z;
            aS[(q4 * 4 + 3) * ALD + kk] = ta.w;
        }
        __syncthreads();

        #pragma unroll 4
        for (int qq = 0; qq < GBQ; qq++) {
            const ull ap = *(const ull*)&aS[qq * ALD + tx * 2];
            #pragma unroll
            for (int i2 = 0; i2 < 4; i2++) {
                ulonglong2 vv = *(const ulonglong2*)&vS[qq * VLD + (ty * 8 + i2 * 2) * 2];
                asm("fma.rn.f32x2 %0, %1, %2, %0;" : "+l"(acc[i2 * 2])     : "l"(vv.x), "l"(ap));
                asm("fma.rn.f32x2 %0, %1, %2, %0;" : "+l"(acc[i2 * 2 + 1]) : "l"(vv.y), "l"(ap));
            }
        }
        __syncthreads();
    }

    float* ob = out + (size_t)b * C_ * NN;
    const int gk = k0 + tx * 2;
    if (gk < NN) {   // gk even, NN even -> gk+1 also valid
        #pragma unroll
        for (int i = 0; i < 8; i++) {
            int c = ty * 8 + i;
            float lo = __uint_as_float((unsigned)(acc[i] & 0xffffffffu));
            float hi = __uint_as_float((unsigned)(acc[i] >> 32));
            atomicAdd(&ob[(size_t)c * NN + gk],     lo);
            atomicAdd(&ob[(size_t)c * NN + gk + 1], hi);
        }
    }
}

// ---------------- Launch ---------------------------------------------------------
extern "C" void kernel_launch(void* const* d_in, const int* in_sizes, int n_in,
                              void* d_out, int out_size) {
    const float* q = (const float*)d_in[0];
    const float* k = (const float*)d_in[1];
    const float* v = (const float*)d_in[2];
    float* out  = (float*)d_out;                      // [B, C, N]
    float* attn = out + (size_t)B_ * C_ * NN;         // [B, N, N]

    (void)in_sizes; (void)n_in; (void)out_size;

    // 0) zero the out region (gemm accumulates with atomics)
    cudaMemsetAsync(out, 0, (size_t)B_ * C_ * NN * sizeof(float), 0);

    // 1) L1 distance logits -> attn region
    dim3 dgrid((NN + DTILE - 1) / DTILE, (NN + DTILE - 1) / DTILE, B_);  // 13,13,2
    dist_kernel<<<dgrid, 256>>>(q, k, attn);

    // 2) softmax over q, in place
    softmax_kernel<<<B_ * NN, 256>>>(attn);

    // 3) out += v @ attn^T (per batch), split-Q x3
    dim3 ggrid((NN + GBN - 1) / GBN, (NN + QSPL - 1) / QSPL, B_);        // 25,3,2
    gemm_kernel<<<ggrid, 256>>>(v, attn, out);
}

// round 8
// speedup vs baseline: 1.6425x; 1.5137x over previous
#include <cuda_runtime.h>
#include <math.h>

// Problem constants
#define B_    2
#define C_    128
#define NN    784
#define INVT  0.08838834764831845f   // 1/sqrt(128)
#define INVC  0.0078125f             // 1/128

typedef unsigned long long ull;

// ================= Distance kernel: attn[b,k,q] = mean_c |q/T - k| =============
// 32x32 tiles, 64-thread blocks, 4x4 micro. Scalar FADD with free |.| modifier.
// 1250 blocks -> high occupancy, good load balance.
#define DQT 32
#define DKT 32
#define DCS 64
#define DLD 36   // 32 + 4 pad

__global__ __launch_bounds__(64) void dist_kernel(const float* __restrict__ q,
                                                  const float* __restrict__ k,
                                                  float* __restrict__ attn) {
    __shared__ float qS[DCS * DLD];
    __shared__ float kS[DCS * DLD];
    const int qt = blockIdx.x * DQT;
    const int kt = blockIdx.y * DKT;
    const int b  = blockIdx.z;
    const int tid = threadIdx.x;
    const int tx = tid & 7;     // q micro: tx*4 .. +3
    const int ty = tid >> 3;    // k micro: ty*4 .. +3

    const float* qb = q + (size_t)b * C_ * NN;
    const float* kb = k + (size_t)b * C_ * NN;

    float acc[4][4];
    #pragma unroll
    for (int j = 0; j < 4; j++)
        #pragma unroll
        for (int i = 0; i < 4; i++) acc[j][i] = 0.f;

    #pragma unroll
    for (int cc = 0; cc < C_; cc += DCS) {
        // stage q tile (scaled): 64c x 8 float4 = 512 float4 over 64 threads
        #pragma unroll
        for (int t = 0; t < 8; t++) {
            int i = tid + t * 64;
            int c = i >> 3, col = i & 7;
            int gq = qt + col * 4;
            float4 qv = make_float4(0.f, 0.f, 0.f, 0.f);
            if (gq < NN) qv = *(const float4*)&qb[(size_t)(cc + c) * NN + gq];
            float* qr = &qS[c * DLD + col * 4];
            qr[0] = qv.x * INVT; qr[1] = qv.y * INVT;
            qr[2] = qv.z * INVT; qr[3] = qv.w * INVT;
        }
        // stage k tile
        #pragma unroll
        for (int t = 0; t < 8; t++) {
            int i = tid + t * 64;
            int c = i >> 3, col = i & 7;
            int gk = kt + col * 4;
            float4 kv = make_float4(0.f, 0.f, 0.f, 0.f);
            if (gk < NN) kv = *(const float4*)&kb[(size_t)(cc + c) * NN + gk];
            float* kr = &kS[c * DLD + col * 4];
            kr[0] = kv.x; kr[1] = kv.y; kr[2] = kv.z; kr[3] = kv.w;
        }
        __syncthreads();

        #pragma unroll 8
        for (int c = 0; c < DCS; c++) {
            float4 qv = *(const float4*)&qS[c * DLD + tx * 4];
            float4 kv = *(const float4*)&kS[c * DLD + ty * 4];
            float qa[4] = {qv.x, qv.y, qv.z, qv.w};
            float ka[4] = {kv.x, kv.y, kv.z, kv.w};
            #pragma unroll
            for (int j = 0; j < 4; j++)
                #pragma unroll
                for (int i = 0; i < 4; i++)
                    acc[j][i] += fabsf(qa[i] - ka[j]);
        }
        __syncthreads();
    }

    float* ab = attn + (size_t)b * NN * NN;
    const int gq = qt + tx * 4;
    if (gq < NN) {
        #pragma unroll
        for (int j = 0; j < 4; j++) {
            int gk = kt + ty * 4 + j;
            if (gk < NN) {
                float4 o = make_float4(acc[j][0] * INVC, acc[j][1] * INVC,
                                       acc[j][2] * INVC, acc[j][3] * INVC);
                *(float4*)&ab[(size_t)gk * NN + gq] = o;
            }
        }
    }
}

// ================= Softmax over last dim (q), in place ========================
__global__ __launch_bounds__(256) void softmax_kernel(float* __restrict__ attn) {
    __shared__ float red[8];
    const int row = blockIdx.x;
    float* p = attn + (size_t)row * NN;
    const int tid  = threadIdx.x;
    const bool act = (tid < NN / 4);   // 196 active lanes

    float4 v = make_float4(-1e30f, -1e30f, -1e30f, -1e30f);
    if (act) v = ((const float4*)p)[tid];

    float mx = fmaxf(fmaxf(v.x, v.y), fmaxf(v.z, v.w));
    #pragma unroll
    for (int o = 16; o > 0; o >>= 1) mx = fmaxf(mx, __shfl_xor_sync(0xffffffffu, mx, o));
    if ((tid & 31) == 0) red[tid >> 5] = mx;
    __syncthreads();
    if (tid < 32) {
        float m = (tid < 8) ? red[tid] : -1e30f;
        #pragma unroll
        for (int o = 4; o > 0; o >>= 1) m = fmaxf(m, __shfl_xor_sync(0xffffffffu, m, o));
        if (tid == 0) red[0] = m;
    }
    __syncthreads();
    mx = red[0];
    __syncthreads();

    v.x = __expf(v.x - mx); v.y = __expf(v.y - mx);
    v.z = __expf(v.z - mx); v.w = __expf(v.w - mx);
    float s = act ? (v.x + v.y) + (v.z + v.w) : 0.f;
    #pragma unroll
    for (int o = 16; o > 0; o >>= 1) s += __shfl_xor_sync(0xffffffffu, s, o);
    if ((tid & 31) == 0) red[tid >> 5] = s;
    __syncthreads();
    if (tid < 32) {
        float m = (tid < 8) ? red[tid] : 0.f;
        #pragma unroll
        for (int o = 4; o > 0; o >>= 1) m += __shfl_xor_sync(0xffffffffu, m, o);
        if (tid == 0) red[0] = m;
    }
    __syncthreads();
    const float inv = 1.f / red[0];
    if (act) {
        v.x *= inv; v.y *= inv; v.z *= inv; v.w *= inv;
        ((float4*)p)[tid] = v;
    }
}

// ================= GEMM: out[b,c,k] = sum_q v[b,c,q] * attn[b,k,q] ============
// Stage 1: tiles of 128c x 112k, 21 q-splits, FFMA2 with register-dup of attn.
// Partials to __device__ scratch; stage 2 reduces. All shapes divide exactly.
#define GTHR   224
#define GTN    112
#define GBQ    16
#define NSPLIT 21
#define NCH    49          // 784/16 q-chunks
#define VLDg   132         // 128 + 4
#define ALDg   116         // 112 + 4
#define PTILE  (128 * 112) // 14336

__device__ float g_part[(size_t)B_ * NSPLIT * 7 * PTILE];

__global__ __launch_bounds__(GTHR) void gemm1_kernel(const float* __restrict__ v,
                                                     const float* __restrict__ attn) {
    __shared__ float vS[GBQ * VLDg];   // [q][c]
    __shared__ float aS[GBQ * ALDg];   // [q][k]
    const int ktile = blockIdx.x;      // 0..6
    const int s     = blockIdx.y;      // 0..20
    const int b     = blockIdx.z;
    const int tid = threadIdx.x;
    const int tx = tid % 28;           // k: tx*4 .. +3
    const int ty = tid / 28;           // c: ty*16 .. +15

    const float* vb = v    + (size_t)b * C_ * NN;
    const float* ab = attn + (size_t)b * NN * NN + (size_t)ktile * GTN * NN;

    ull acc[8][4];
    #pragma unroll
    for (int p = 0; p < 8; p++)
        #pragma unroll
        for (int j = 0; j < 4; j++) acc[p][j] = 0ULL;

    const int ch0 = (s * NCH) / NSPLIT;
    const int ch1 = ((s + 1) * NCH) / NSPLIT;

    for (int ch = ch0; ch < ch1; ch++) {
        const int q0 = ch * GBQ;
        // stage v: 128c x 16q = 512 float4
        for (int i = tid; i < 512; i += GTHR) {
            int c = i >> 2, q4 = i & 3;
            float4 t = *(const float4*)&vb[(size_t)c * NN + q0 + q4 * 4];
            vS[(q4 * 4 + 0) * VLDg + c] = t.x;
            vS[(q4 * 4 + 1) * VLDg + c] = t.y;
            vS[(q4 * 4 + 2) * VLDg + c] = t.z;
            vS[(q4 * 4 + 3) * VLDg + c] = t.w;
        }
        // stage a: 112k x 16q = 448 float4
        for (int i = tid; i < 448; i += GTHR) {
            int kk = i >> 2, q4 = i & 3;
            float4 t = *(const float4*)&ab[(size_t)kk * NN + q0 + q4 * 4];
            aS[(q4 * 4 + 0) * ALDg + kk] = t.x;
            aS[(q4 * 4 + 1) * ALDg + kk] = t.y;
            aS[(q4 * 4 + 2) * ALDg + kk] = t.z;
            aS[(q4 * 4 + 3) * ALDg + kk] = t.w;
        }
        __syncthreads();

        #pragma unroll 4
        for (int qq = 0; qq < GBQ; qq++) {
            float4 a4 = *(const float4*)&aS[qq * ALDg + tx * 4];
            ull d[4];
            asm("mov.b64 %0, {%1, %1};" : "=l"(d[0]) : "f"(a4.x));
            asm("mov.b64 %0, {%1, %1};" : "=l"(d[1]) : "f"(a4.y));
            asm("mov.b64 %0, {%1, %1};" : "=l"(d[2]) : "f"(a4.z));
            asm("mov.b64 %0, {%1, %1};" : "=l"(d[3]) : "f"(a4.w));
            const float* vrow = &vS[qq * VLDg + ty * 16];
            float4 v0 = *(const float4*)(vrow + 0);
            float4 v1 = *(const float4*)(vrow + 4);
            float4 v2 = *(const float4*)(vrow + 8);
            float4 v3 = *(const float4*)(vrow + 12);
            ull vp[8];
            vp[0] = ((const ull*)&v0)[0]; vp[1] = ((const ull*)&v0)[1];
            vp[2] = ((const ull*)&v1)[0]; vp[3] = ((const ull*)&v1)[1];
            vp[4] = ((const ull*)&v2)[0]; vp[5] = ((const ull*)&v2)[1];
            vp[6] = ((const ull*)&v3)[0]; vp[7] = ((const ull*)&v3)[1];
            #pragma unroll
            for (int p = 0; p < 8; p++) {
                #pragma unroll
                for (int j = 0; j < 4; j++)
                    asm("fma.rn.f32x2 %0, %1, %2, %0;"
                        : "+l"(acc[p][j]) : "l"(vp[p]), "l"(d[j]));
            }
        }
        __syncthreads();
    }

    // write partials: [c][112k] tile layout, float4 along k
    float* base = g_part + (((size_t)(b * NSPLIT + s) * 7) + ktile) * PTILE;
    #pragma unroll
    for (int p = 0; p < 8; p++) {
        int c0 = ty * 16 + p * 2;
        float4 lo, hi;
        lo.x = __uint_as_float((unsigned)(acc[p][0] & 0xffffffffu));
        lo.y = __uint_as_float((unsigned)(acc[p][1] & 0xffffffffu));
        lo.z = __uint_as_float((unsigned)(acc[p][2] & 0xffffffffu));
        lo.w = __uint_as_float((unsigned)(acc[p][3] & 0xffffffffu));
        hi.x = __uint_as_float((unsigned)(acc[p][0] >> 32));
        hi.y = __uint_as_float((unsigned)(acc[p][1] >> 32));
        hi.z = __uint_as_float((unsigned)(acc[p][2] >> 32));
        hi.w = __uint_as_float((unsigned)(acc[p][3] >> 32));
        *(float4*)&base[(size_t)c0 * GTN + tx * 4]       = lo;
        *(float4*)&base[(size_t)(c0 + 1) * GTN + tx * 4] = hi;
    }
}

__global__ __launch_bounds__(256) void gemm2_kernel(float* __restrict__ out) {
    const int idx = blockIdx.x * 256 + threadIdx.x;   // float4 index
    const int total4 = B_ * C_ * NN / 4;              // 50176
    if (idx >= total4) return;
    const int per_b = C_ * NN / 4;                    // 25088
    const int b = idx / per_b;
    const int e = (idx % per_b) * 4;
    const int c  = e / NN;
    const int kk = e % NN;
    const int kt = kk / GTN, kl = kk % GTN;           // float4 never crosses kt (112%4==0)
    const float* src = g_part + (((size_t)(b * NSPLIT) * 7) + kt) * PTILE
                     + (size_t)c * GTN + kl;
    float4 s = make_float4(0.f, 0.f, 0.f, 0.f);
    #pragma unroll
    for (int sp = 0; sp < NSPLIT; sp++) {
        float4 t = *(const float4*)(src + (size_t)sp * 7 * PTILE);
        s.x += t.x; s.y += t.y; s.z += t.z; s.w += t.w;
    }
    ((float4*)out)[idx] = s;
}

// ================= Launch ======================================================
extern "C" void kernel_launch(void* const* d_in, const int* in_sizes, int n_in,
                              void* d_out, int out_size) {
    const float* q = (const float*)d_in[0];
    const float* k = (const float*)d_in[1];
    const float* v = (const float*)d_in[2];
    float* out  = (float*)d_out;                      // [B, C, N]
    float* attn = out + (size_t)B_ * C_ * NN;         // [B, N, N]

    (void)in_sizes; (void)n_in; (void)out_size;

    // 1) L1 distance logits -> attn region (25x25x2 = 1250 blocks)
    dim3 dgrid((NN + DQT - 1) / DQT, (NN + DKT - 1) / DKT, B_);
    dist_kernel<<<dgrid, 64>>>(q, k, attn);

    // 2) softmax over q, in place
    softmax_kernel<<<B_ * NN, 256>>>(attn);

    // 3) out = v @ attn^T : split-q partials, then reduce
    dim3 g1(7, NSPLIT, B_);                           // 294 blocks = ~2/SM
    gemm1_kernel<<<g1, GTHR>>>(v, attn);
    gemm2_kernel<<<(B_ * C_ * NN / 4 + 255) / 256, 256>>>(out);
}